// round 13
// baseline (speedup 1.0000x reference)
#include <cuda_runtime.h>
#include <cuda_fp16.h>
#include <cstdint>

#define NSITES   262144
#define CCH      64
#define BN_EPS_F 1e-3f
#define NCTA     2048        // conv CTAs (= NSITES/128), BN partials count
#define FIN1     64          // finalize blocks
#define FEATBLK  (NSITES * 64 / 8 / 256)   // 8192 blocks for feature convert
#define WFRAGN   (9 * 8 * 4 * 32)          // 9216 uint2 fragments

// ---------------- scratch (__device__ globals; no allocations) ----------------
__device__ __align__(128) __half g_f16[NSITES * 64];     // features, fp16
__device__ __align__(128) uint2  g_wfrag[WFRAGN];        // B fragments, mma-lane order
__device__ float g_psum[NCTA * CCH];
__device__ float g_psq [NCTA * CCH];
__device__ float g_ps2 [FIN1 * CCH];
__device__ float g_pq2 [FIN1 * CCH];
__device__ float g_scale[CCH];
__device__ float g_shift[CCH];
__device__ unsigned int g_cnt;                           // finalize arrival counter

// ---------------- helpers ----------------
__device__ __forceinline__ uint32_t smem_u32(const void* p) {
    uint32_t a;
    asm("{ .reg .u64 t; cvta.to.shared.u64 t, %1; cvt.u32.u64 %0, t; }" : "=r"(a) : "l"(p));
    return a;
}
__device__ __forceinline__ void ldsm_x4(uint32_t& r0, uint32_t& r1, uint32_t& r2, uint32_t& r3,
                                        uint32_t addr) {
    asm volatile("ldmatrix.sync.aligned.m8n8.x4.shared.b16 {%0,%1,%2,%3}, [%4];"
                 : "=r"(r0), "=r"(r1), "=r"(r2), "=r"(r3) : "r"(addr));
}
__device__ __forceinline__ void mma_f16(float* d, const uint32_t* a, uint32_t b0, uint32_t b1) {
    asm volatile(
        "mma.sync.aligned.m16n8k16.row.col.f32.f16.f16.f32 "
        "{%0,%1,%2,%3}, {%4,%5,%6,%7}, {%8,%9}, {%0,%1,%2,%3};"
        : "+f"(d[0]), "+f"(d[1]), "+f"(d[2]), "+f"(d[3])
        : "r"(a[0]), "r"(a[1]), "r"(a[2]), "r"(a[3]), "r"(b0), "r"(b1));
}
#define CP_ASYNC16(dst, src, sz) \
    asm volatile("cp.async.cg.shared.global [%0], [%1], 16, %2;" \
                 :: "r"(dst), "l"(src), "r"(sz) : "memory")
#define CP_COMMIT()  asm volatile("cp.async.commit_group;" ::: "memory")
#define CP_WAITG4()  asm volatile("cp.async.wait_group 4;" ::: "memory")

// ---------------- precompute: features -> fp16 ; weights -> lane-order fragments ----------------
__global__ __launch_bounds__(256) void split_all(const float* __restrict__ f,
                                                 const float* __restrict__ w)
{
    if (blockIdx.x < FEATBLK) {
        size_t i = ((size_t)blockIdx.x * 256 + threadIdx.x) * 8;
        float4 a = *(const float4*)(f + i);
        float4 b = *(const float4*)(f + i + 4);
        float v[8] = {a.x, a.y, a.z, a.w, b.x, b.y, b.z, b.w};
        __half h[8];
        #pragma unroll
        for (int j = 0; j < 8; ++j) h[j] = __float2half_rn(v[j]);
        *(uint4*)(g_f16 + i) = *(uint4*)h;
    } else {
        int i = (blockIdx.x - FEATBLK) * 256 + threadIdx.x;   // 0..9215
        if (i < WFRAGN) {
            int lane = i & 31, ks = (i >> 5) & 3, n8 = (i >> 7) & 7, k = i >> 10;
            int n  = n8 * 8 + (lane >> 2);
            int k0 = ks * 16 + (lane & 3) * 2;
            const float* wk = w + ((size_t)k << 12);          // [cin][cout], cout contig
            uint32_t lo0 = __half_as_ushort(__float2half_rn(wk[(k0    ) * 64 + n]));
            uint32_t hi0 = __half_as_ushort(__float2half_rn(wk[(k0 + 1) * 64 + n]));
            uint32_t lo1 = __half_as_ushort(__float2half_rn(wk[(k0 + 8) * 64 + n]));
            uint32_t hi1 = __half_as_ushort(__float2half_rn(wk[(k0 + 9) * 64 + n]));
            g_wfrag[i] = make_uint2(lo0 | (hi0 << 16), lo1 | (hi1 << 16));
        }
    }
}

// ---------------- conv: 6-stage A pipeline (cp.async) + fp16 HMMA, B from L1 ----------------
// Dynamic SMEM (96 KB): A stages 6 x 16384
#define STAGE_A   16384
#define SMEM_CONV 98304

__global__ __launch_bounds__(256, 2) void conv_hmma(
    const int*   __restrict__ nbr,
    const float* __restrict__ bias,
    float*       __restrict__ out)
{
    extern __shared__ __align__(128) char smem[];
    const uint32_t sb = smem_u32(smem);

    const int tid  = threadIdx.x;
    const int wid  = tid >> 5;
    const int l    = tid & 31;
    const int WM   = wid >> 1;           // 0..3 : 32-row slice
    const int WN   = wid & 1;            // 0..1 : 32-col slice
    const int base = blockIdx.x * 128;

    const int site = tid >> 1;           // 2 threads per site
    const int half = tid & 1;
    const int akey = site & 7;

    int rows9[9];
    #pragma unroll
    for (int k = 0; k < 9; ++k)
        rows9[k] = nbr[(size_t)(base + site) * 9 + k];

    auto issue_A = [&](int row, int st) {
        uint32_t aD = sb + st * STAGE_A + (uint32_t)(site * 128);
        size_t r = (size_t)(row >= 0 ? row : 0);
        const char* src = (const char*)(g_f16 + r * 64 + half * 32);
        int sz = (row >= 0) ? 16 : 0;
        #pragma unroll
        for (int j = 0; j < 4; ++j) {
            int chunk = half * 4 + j;
            uint32_t sw = (uint32_t)((chunk ^ akey) * 16);
            CP_ASYNC16(aD + sw, src + j * 16, sz);
        }
    };

    // prologue: taps 0..4 in flight (stages 0..4)
    #pragma unroll
    for (int kk = 0; kk < 5; ++kk) {
        issue_A(rows9[kk], kk);
        CP_COMMIT();
    }

    float d[2][4][4];
    #pragma unroll
    for (int mt = 0; mt < 2; ++mt)
        #pragma unroll
        for (int nt = 0; nt < 4; ++nt)
            #pragma unroll
            for (int j = 0; j < 4; ++j) d[mt][nt][j] = 0.0f;

    const int aRow = l & 15;
    const int aCB  = (l >> 4) & 1;
    const int aKey = l & 7;
    uint32_t aOffRow[2];
    #pragma unroll
    for (int mt = 0; mt < 2; ++mt)
        aOffRow[mt] = (uint32_t)((WM * 32 + mt * 16 + aRow) * 128);

    // per-lane B fragment base: index ((k*8 + n8)*4 + ks)*32 + l
    const uint2* __restrict__ wf = g_wfrag;

    int stage = 0;                        // k % 6
    for (int k = 0; k < 9; ++k) {
        const int kk = k + 5;
        int stIn = stage + 5; if (stIn >= 6) stIn -= 6;      // (k+5) % 6

        CP_WAITG4();                      // tap k's group complete (<=4 pending)
        __syncthreads();                  // data visible; stage stIn free (tap k-1 done)

        if (kk < 9) {                     // refill 5 taps ahead
            issue_A(rows9[kk], stIn);
        }
        CP_COMMIT();

        const uint32_t aBase = sb + (uint32_t)(stage * STAGE_A);
        const int kb = k * 8 + WN * 4;    // first n8 block for this warp

        #pragma unroll
        for (int ks = 0; ks < 4; ++ks) {
            // B fragments straight from global (L1-resident, static addresses)
            uint2 bv[4];
            #pragma unroll
            for (int f4 = 0; f4 < 4; ++f4)
                bv[f4] = wf[((kb + f4) * 4 + ks) * 32 + l];

            uint32_t a[2][4];
            uint32_t swA = (uint32_t)(((ks * 2 + aCB) ^ aKey) << 4);
            #pragma unroll
            for (int mt = 0; mt < 2; ++mt)
                ldsm_x4(a[mt][0], a[mt][1], a[mt][2], a[mt][3],
                        aBase + aOffRow[mt] + swA);

            #pragma unroll
            for (int mt = 0; mt < 2; ++mt)
                #pragma unroll
                for (int f4 = 0; f4 < 4; ++f4)
                    mma_f16(d[mt][f4], a[mt], bv[f4].x, bv[f4].y);
        }

        stage = (stage + 1 >= 6) ? 0 : stage + 1;
    }

    // ---- epilogue: bias add, store, per-CTA BN partials ----
    float colS[4][2], colQ[4][2];
    #pragma unroll
    for (int nt = 0; nt < 4; ++nt) {
        int col = WN * 32 + nt * 8 + 2 * (l & 3);
        float b0 = bias[col], b1 = bias[col + 1];
        float s0 = 0.f, q0 = 0.f, s1 = 0.f, q1 = 0.f;
        #pragma unroll
        for (int mt = 0; mt < 2; ++mt) {
            int r0 = base + WM * 32 + mt * 16 + (l >> 2);
            float x0 = d[mt][nt][0] + b0, x1 = d[mt][nt][1] + b1;
            float x2 = d[mt][nt][2] + b0, x3 = d[mt][nt][3] + b1;
            *(float2*)(out + (size_t)r0 * 64 + col)       = make_float2(x0, x1);
            *(float2*)(out + (size_t)(r0 + 8) * 64 + col) = make_float2(x2, x3);
            s0 += x0 + x2;  q0 += x0 * x0 + x2 * x2;
            s1 += x1 + x3;  q1 += x1 * x1 + x3 * x3;
        }
        colS[nt][0] = s0; colS[nt][1] = s1;
        colQ[nt][0] = q0; colQ[nt][1] = q1;
    }
    #pragma unroll
    for (int off = 4; off <= 16; off <<= 1)
        #pragma unroll
        for (int nt = 0; nt < 4; ++nt)
            #pragma unroll
            for (int c = 0; c < 2; ++c) {
                colS[nt][c] += __shfl_xor_sync(0xffffffffu, colS[nt][c], off);
                colQ[nt][c] += __shfl_xor_sync(0xffffffffu, colQ[nt][c], off);
            }

    // overlay in STAGE-3 A region (last consumed at tap 3; taps 6..8 used stages 0..2)
    float* warpS = (float*)(smem + 3 * STAGE_A);          // [8][32]
    float* warpQ = (float*)(smem + 3 * STAGE_A + 1024);   // [8][32]
    if (l < 4) {
        #pragma unroll
        for (int nt = 0; nt < 4; ++nt) {
            warpS[wid * 32 + nt * 8 + 2 * l]     = colS[nt][0];
            warpS[wid * 32 + nt * 8 + 2 * l + 1] = colS[nt][1];
            warpQ[wid * 32 + nt * 8 + 2 * l]     = colQ[nt][0];
            warpQ[wid * 32 + nt * 8 + 2 * l + 1] = colQ[nt][1];
        }
    }
    __syncthreads();
    if (tid < 128) {
        int ch = tid & 63, kind = tid >> 6;
        int wn = ch >> 5, idx = ch & 31;
        const float* src = kind ? warpQ : warpS;
        float v = src[(0 * 2 + wn) * 32 + idx] + src[(1 * 2 + wn) * 32 + idx]
                + src[(2 * 2 + wn) * 32 + idx] + src[(3 * 2 + wn) * 32 + idx];
        if (kind) g_psq [blockIdx.x * 64 + ch] = v;
        else      g_psum[blockIdx.x * 64 + ch] = v;
    }
}

// ---------------- BN finalize: fused two-level, last block computes scale/shift ----------------
__global__ __launch_bounds__(256) void bn_fin(const float* __restrict__ gamma,
                                              const float* __restrict__ beta)
{
    __shared__ float ss[4][64], sq[4][64];
    __shared__ int last;
    const int ch = threadIdx.x & 63;
    const int g  = threadIdx.x >> 6;

    float s = 0.f, q = 0.f;
    #pragma unroll
    for (int i = g; i < NCTA / FIN1; i += 4) {
        int idx = (blockIdx.x * (NCTA / FIN1) + i) * 64 + ch;
        s += g_psum[idx];
        q += g_psq [idx];
    }
    ss[g][ch] = s; sq[g][ch] = q;
    __syncthreads();
    if (g == 0) {
        g_ps2[blockIdx.x * 64 + ch] = ss[0][ch] + ss[1][ch] + ss[2][ch] + ss[3][ch];
        g_pq2[blockIdx.x * 64 + ch] = sq[0][ch] + sq[1][ch] + sq[2][ch] + sq[3][ch];
    }
    __threadfence();
    __syncthreads();
    if (threadIdx.x == 0)
        last = (atomicAdd(&g_cnt, 1u) == FIN1 - 1);
    __syncthreads();

    if (last) {
        float s2 = 0.f, q2 = 0.f;
        #pragma unroll
        for (int i = g; i < FIN1; i += 4) {
            s2 += g_ps2[i * 64 + ch];
            q2 += g_pq2[i * 64 + ch];
        }
        ss[g][ch] = s2; sq[g][ch] = q2;
        __syncthreads();
        if (g == 0) {
            s2 = ss[0][ch] + ss[1][ch] + ss[2][ch] + ss[3][ch];
            q2 = sq[0][ch] + sq[1][ch] + sq[2][ch] + sq[3][ch];
            const float inv_n = 1.0f / (float)NSITES;
            float mean = s2 * inv_n;
            float var  = q2 * inv_n - mean * mean;
            float sc   = gamma[ch] * rsqrtf(var + BN_EPS_F);
            g_scale[ch] = sc;
            g_shift[ch] = beta[ch] - mean * sc;
        }
        if (threadIdx.x == 0) g_cnt = 0;   // reset for next graph replay
    }
}

// ---------------- BN apply: 2 float4 per thread, streaming stores ----------------
__global__ __launch_bounds__(256) void bn_apply(const float* __restrict__ out,
                                                float* __restrict__ outbn)
{
    size_t i0 = ((size_t)blockIdx.x * 256 + threadIdx.x) * 2;
    #pragma unroll
    for (int j = 0; j < 2; ++j) {
        size_t i = i0 + j;
        float4 v = ((const float4*)out)[i];
        int cb = ((int)(i & 15)) * 4;
        float4 sc = *(const float4*)&g_scale[cb];
        float4 sh = *(const float4*)&g_shift[cb];
        float4 o = make_float4(v.x * sc.x + sh.x, v.y * sc.y + sh.y,
                               v.z * sc.z + sh.z, v.w * sc.w + sh.w);
        __stwt((float4*)outbn + i, o);
    }
}

// ---------------- launch ----------------
extern "C" void kernel_launch(void* const* d_in, const int* in_sizes, int n_in,
                              void* d_out, int out_size)
{
    const float* feat  = (const float*)d_in[0];
    const float* w     = (const float*)d_in[1];
    const float* bias  = (const float*)d_in[2];
    const float* gamma = (const float*)d_in[3];
    const float* beta  = (const float*)d_in[4];
    const int*   nbr   = (const int*)  d_in[5];

    float* out   = (float*)d_out;
    float* outbn = out + (size_t)NSITES * CCH;

    cudaFuncSetAttribute(conv_hmma, cudaFuncAttributeMaxDynamicSharedMemorySize, SMEM_CONV);

    split_all <<<FEATBLK + 36, 256>>>(feat, w);
    conv_hmma <<<NCTA, 256, SMEM_CONV>>>(nbr, bias, out);
    bn_fin    <<<FIN1, 256>>>(gamma, beta);
    bn_apply  <<<(NSITES * CCH / 8) / 256, 256>>>(out, outbn);
}